// round 2
// baseline (speedup 1.0000x reference)
#include <cuda_runtime.h>
#include <math.h>

#define BB 16
#define LL 320
#define DM 192
#define DI 384
#define DS 16
#define DR 12
#define DEPTH 24
#define NROWS (BB*LL)      /* 5120 */
#define NC 10
#define CL 32
#define LOG2E 1.4426950408889634f
#define EPSLN 1e-5f

/* ---------------- scratch (static device globals; no allocation) -------- */
__device__ float g_hidden[NROWS*DM];
__device__ float g_res[NROWS*DM];
__device__ float g_hn[NROWS*DM];
__device__ float g_xz[NROWS*2*DI];
__device__ float g_xc[NROWS*DI];
__device__ float g_dbl[NROWS*44];
__device__ float g_dt[NROWS*DI];
__device__ float g_y[NROWS*DI];
__device__ float g_eend[BB*NC*DI*DS];
__device__ float g_S[BB*NC*DI];
__device__ float g_cin[BB*NC*DI*DS];

/* ---------------- patch embed + pos, zero residual ---------------------- */
/* grid: NROWS/4 blocks, 192 threads. Each block: 4 tokens, thread = d.     */
__global__ __launch_bounds__(192) void patch_kernel(
    const float* __restrict__ ximg, const float* __restrict__ zimg,
    const float* __restrict__ pw, const float* __restrict__ pb,
    const float* __restrict__ posx, const float* __restrict__ posz,
    float* __restrict__ hidden, float* __restrict__ res)
{
    __shared__ float sp[4][768];
    int tg = blockIdx.x, tid = threadIdx.x;
    for (int i = 0; i < 4; i++) {
        int r = tg*4 + i, b = r / LL, t = r % LL;
        for (int c = tid; c < 768; c += 192) {
            int ch = c >> 8, p = c & 255, py = p >> 4, px = p & 15;
            float v;
            if (t < 64) {
                int ph = (t >> 3)*16 + py, pwi = (t & 7)*16 + px;
                v = zimg[((b*3 + ch)*128 + ph)*128 + pwi];
            } else {
                int tx = t - 64;
                int ph = (tx >> 4)*16 + py, pwi = (tx & 15)*16 + px;
                v = ximg[((b*3 + ch)*256 + ph)*256 + pwi];
            }
            sp[i][c] = v;
        }
    }
    __syncthreads();
    int d = tid;
    float a0 = 0.f, a1 = 0.f, a2 = 0.f, a3 = 0.f;
    const float* wr = pw + d*768;
    for (int c = 0; c < 768; c++) {
        float w = wr[c];
        a0 = fmaf(w, sp[0][c], a0);
        a1 = fmaf(w, sp[1][c], a1);
        a2 = fmaf(w, sp[2][c], a2);
        a3 = fmaf(w, sp[3][c], a3);
    }
    float accs[4] = {a0, a1, a2, a3};
    for (int i = 0; i < 4; i++) {
        int r = tg*4 + i, t = r % LL;
        float pos = (t < 64) ? posz[t*DM + d] : posx[(t - 64)*DM + d];
        hidden[r*DM + d] = accs[i] + pb[d] + pos;
        res[r*DM + d] = 0.f;
    }
}

/* ---------------- fused add + layernorm --------------------------------- */
/* grid NROWS, block 192 (= DM). write_res: store updated residual.        */
__global__ __launch_bounds__(192) void addnorm_kernel(
    const float* __restrict__ hid, float* __restrict__ res,
    const float* __restrict__ w, const float* __restrict__ b,
    float* __restrict__ o, int write_res)
{
    int row = blockIdx.x, d = threadIdx.x;
    float v = hid[row*DM + d] + res[row*DM + d];
    if (write_res) res[row*DM + d] = v;
    float s = v, sq = v*v;
    #pragma unroll
    for (int off = 16; off > 0; off >>= 1) {
        s  += __shfl_down_sync(0xffffffffu, s,  off);
        sq += __shfl_down_sync(0xffffffffu, sq, off);
    }
    __shared__ float sh1[6], sh2[6];
    int wid = d >> 5, lane = d & 31;
    if (lane == 0) { sh1[wid] = s; sh2[wid] = sq; }
    __syncthreads();
    float ts = 0.f, tq = 0.f;
    #pragma unroll
    for (int i = 0; i < 6; i++) { ts += sh1[i]; tq += sh2[i]; }
    float mean = ts * (1.f/DM);
    float var  = tq * (1.f/DM) - mean*mean;
    float rs = rsqrtf(var + EPSLN);
    o[row*DM + d] = (v - mean) * rs * w[d] + b[d];
}

/* ---------------- generic fp32 tiled GEMM: C[M,N] = A[M,K] @ W[N,K]^T --- */
/* BM=BN=64, BK=16, 256 threads, 4x4 per thread. ep: 0 none, 1 softplus.   */
__global__ __launch_bounds__(256) void gemm_kernel(
    const float* __restrict__ A, int lda,
    const float* __restrict__ W,
    float* __restrict__ C, int ldc,
    int M, int N, int K,
    const float* __restrict__ bias, int ep)
{
    __shared__ __align__(16) float As[16][64];
    __shared__ __align__(16) float Ws[16][64];
    int tid = threadIdx.x;
    int bm = blockIdx.y * 64, bn = blockIdx.x * 64;
    int tx = tid & 15, ty = tid >> 4;
    float acc[4][4];
    #pragma unroll
    for (int i = 0; i < 4; i++)
        #pragma unroll
        for (int j = 0; j < 4; j++) acc[i][j] = 0.f;

    for (int k0 = 0; k0 < K; k0 += 16) {
        #pragma unroll
        for (int i = 0; i < 4; i++) {
            int e = tid + i*256;
            int m = e >> 4, k = e & 15;
            float va = 0.f, vw = 0.f;
            if (k0 + k < K) {
                if (bm + m < M) va = A[(size_t)(bm + m)*lda + k0 + k];
                if (bn + m < N) vw = W[(size_t)(bn + m)*K + k0 + k];
            }
            As[k][m] = va;
            Ws[k][m] = vw;
        }
        __syncthreads();
        #pragma unroll
        for (int kk = 0; kk < 16; kk++) {
            float4 a4 = *reinterpret_cast<const float4*>(&As[kk][ty*4]);
            float4 b4 = *reinterpret_cast<const float4*>(&Ws[kk][tx*4]);
            float a[4] = {a4.x, a4.y, a4.z, a4.w};
            float bv[4] = {b4.x, b4.y, b4.z, b4.w};
            #pragma unroll
            for (int i = 0; i < 4; i++)
                #pragma unroll
                for (int j = 0; j < 4; j++)
                    acc[i][j] = fmaf(a[i], bv[j], acc[i][j]);
        }
        __syncthreads();
    }
    #pragma unroll
    for (int i = 0; i < 4; i++) {
        int m = bm + ty*4 + i;
        if (m >= M) continue;
        #pragma unroll
        for (int j = 0; j < 4; j++) {
            int n = bn + tx*4 + j;
            if (n >= N) continue;
            float v = acc[i][j];
            if (bias) v += bias[n];
            if (ep == 1) v = (v > 20.f) ? v : log1pf(expf(v));
            C[(size_t)m*ldc + n] = v;
        }
    }
}

/* ---------------- causal depthwise conv + silu -------------------------- */
__global__ __launch_bounds__(256) void conv_silu_kernel(
    const float* __restrict__ xz, const float* __restrict__ cw,
    const float* __restrict__ cb, float* __restrict__ xc)
{
    int idx = blockIdx.x*blockDim.x + threadIdx.x;
    if (idx >= NROWS*DI) return;
    int d = idx % DI, r = idx / DI;
    int b = r / LL, l = r % LL;
    float acc = cb[d];
    #pragma unroll
    for (int j = 0; j < 4; j++) {
        int ls = l - 3 + j;
        if (ls >= 0)
            acc = fmaf(xz[(size_t)(b*LL + ls)*(2*DI) + d], cw[d*4 + j], acc);
    }
    float sig = 1.f / (1.f + expf(-acc));
    xc[idx] = acc * sig;
}

/* ---------------- scan pass 1: chunk-local scan ------------------------- */
/* grid (NC, BB), block DI. Writes local y, chunk end-state, chunk dt-sum. */
__global__ __launch_bounds__(DI) void scan1_kernel(
    const float* __restrict__ dt, const float* __restrict__ xc,
    const float* __restrict__ dbl, const float* __restrict__ A_log,
    float* __restrict__ y, float* __restrict__ eend, float* __restrict__ S)
{
    int b = blockIdx.y, ck = blockIdx.x, d = threadIdx.x;
    __shared__ float sB[CL][DS], sC[CL][DS];
    for (int e = d; e < CL*DS; e += DI) {
        int l = e >> 4, n = e & 15;
        const float* row = dbl + (size_t)(b*LL + ck*CL + l)*44;
        sB[l][n] = row[12 + n];
        sC[l][n] = row[28 + n];
    }
    __syncthreads();
    float cn[DS], h[DS];
    const float* al = A_log + d*DS;
    #pragma unroll
    for (int n = 0; n < DS; n++) { cn[n] = -expf(al[n]) * LOG2E; h[n] = 0.f; }
    float Ss = 0.f;
    int base = (b*LL + ck*CL)*DI + d;
    for (int l = 0; l < CL; l++) {
        float dtv = dt[base + l*DI];
        float xcv = xc[base + l*DI];
        Ss += dtv;
        float u = dtv * xcv;
        float acc = 0.f;
        #pragma unroll
        for (int n = 0; n < DS; n++) {
            float e2 = exp2f(dtv * cn[n]);
            h[n] = fmaf(e2, h[n], u * sB[l][n]);
            acc = fmaf(h[n], sC[l][n], acc);
        }
        y[base + l*DI] = acc;
    }
    int si = (b*NC + ck)*DI + d;
    S[si] = Ss;
    #pragma unroll
    for (int n = 0; n < DS; n++) eend[(size_t)si*DS + n] = h[n];
}

/* ---------------- carry propagation across chunks ----------------------- */
__global__ __launch_bounds__(256) void carry_kernel(
    const float* __restrict__ eend, const float* __restrict__ S,
    const float* __restrict__ A_log, float* __restrict__ cin)
{
    int idx = blockIdx.x*blockDim.x + threadIdx.x;
    if (idx >= BB*DI*DS) return;
    int n = idx & 15, d = (idx >> 4) % DI, b = idx / (DI*DS);
    float cf = -expf(A_log[d*DS + n]) * LOG2E;
    float c = 0.f;
    for (int k = 0; k < NC; k++) {
        int si = (b*NC + k)*DI + d;
        cin[(size_t)si*DS + n] = c;
        c = fmaf(exp2f(S[si] * cf), c, eend[(size_t)si*DS + n]);
    }
}

/* ---------------- scan pass 3: carry correction + D skip + z gate ------- */
__global__ __launch_bounds__(DI) void scan3_kernel(
    const float* __restrict__ dt, const float* __restrict__ dbl,
    const float* __restrict__ A_log, const float* __restrict__ cin,
    const float* __restrict__ xz, const float* __restrict__ xc,
    const float* __restrict__ Dsk, float* __restrict__ y)
{
    int b = blockIdx.y, ck = blockIdx.x, d = threadIdx.x;
    __shared__ float sC[CL][DS];
    for (int e = d; e < CL*DS; e += DI) {
        int l = e >> 4, n = e & 15;
        sC[l][n] = dbl[(size_t)(b*LL + ck*CL + l)*44 + 28 + n];
    }
    __syncthreads();
    float cn[DS], ci[DS];
    if (ck > 0) {
        const float* al = A_log + d*DS;
        const float* cp = cin + (size_t)((b*NC + ck)*DI + d)*DS;
        #pragma unroll
        for (int n = 0; n < DS; n++) { cn[n] = -expf(al[n]) * LOG2E; ci[n] = cp[n]; }
    }
    float Dv = Dsk[d];
    int base = (b*LL + ck*CL)*DI + d;
    float tau = 0.f;
    for (int l = 0; l < CL; l++) {
        float dtv = dt[base + l*DI];
        tau += dtv;
        float yv = y[base + l*DI];
        if (ck > 0) {
            #pragma unroll
            for (int n = 0; n < DS; n++)
                yv = fmaf(exp2f(tau * cn[n]) * ci[n], sC[l][n], yv);
        }
        yv = fmaf(xc[base + l*DI], Dv, yv);
        int row = b*LL + ck*CL + l;
        float zv = xz[(size_t)row*(2*DI) + DI + d];
        yv *= zv / (1.f + expf(-zv));
        y[base + l*DI] = yv;
    }
}

/* ---------------- host driver ------------------------------------------- */
extern "C" void kernel_launch(void* const* d_in, const int* in_sizes, int n_in,
                              void* d_out, int out_size)
{
    const float* x_img   = (const float*)d_in[0];
    const float* z_img   = (const float*)d_in[1];
    const float* patch_w = (const float*)d_in[2];
    const float* patch_b = (const float*)d_in[3];
    const float* pos_x   = (const float*)d_in[4];
    const float* pos_z   = (const float*)d_in[5];
    const float* ln_w    = (const float*)d_in[6];
    const float* ln_b    = (const float*)d_in[7];
    const float* in_w    = (const float*)d_in[8];
    const float* conv_w  = (const float*)d_in[9];
    const float* conv_b  = (const float*)d_in[10];
    const float* xproj_w = (const float*)d_in[11];
    const float* dt_w    = (const float*)d_in[12];
    const float* dt_b    = (const float*)d_in[13];
    const float* A_log   = (const float*)d_in[14];
    const float* D_skip  = (const float*)d_in[15];
    const float* out_w   = (const float*)d_in[16];
    const float* fnorm_w = (const float*)d_in[17];
    const float* fnorm_b = (const float*)d_in[18];
    float* out = (float*)d_out;

    float *hidden, *res, *hn, *xz, *xc, *dbl, *dt, *y, *eend, *S, *cin;
    cudaGetSymbolAddress((void**)&hidden, g_hidden);
    cudaGetSymbolAddress((void**)&res,    g_res);
    cudaGetSymbolAddress((void**)&hn,     g_hn);
    cudaGetSymbolAddress((void**)&xz,     g_xz);
    cudaGetSymbolAddress((void**)&xc,     g_xc);
    cudaGetSymbolAddress((void**)&dbl,    g_dbl);
    cudaGetSymbolAddress((void**)&dt,     g_dt);
    cudaGetSymbolAddress((void**)&y,      g_y);
    cudaGetSymbolAddress((void**)&eend,   g_eend);
    cudaGetSymbolAddress((void**)&S,      g_S);
    cudaGetSymbolAddress((void**)&cin,    g_cin);

    patch_kernel<<<NROWS/4, 192>>>(x_img, z_img, patch_w, patch_b,
                                   pos_x, pos_z, hidden, res);

    for (int l = 0; l < DEPTH; l++) {
        addnorm_kernel<<<NROWS, 192>>>(hidden, res, ln_w + l*DM, ln_b + l*DM, hn, 1);

        /* in_proj: (5120,192) @ (768,192)^T -> xz (5120,768) */
        gemm_kernel<<<dim3(12, 80), 256>>>(hn, DM, in_w + (size_t)l*2*DI*DM,
                                           xz, 2*DI, NROWS, 2*DI, DM, nullptr, 0);

        conv_silu_kernel<<<(NROWS*DI + 255)/256, 256>>>(xz, conv_w + l*DI*4,
                                                        conv_b + l*DI, xc);

        /* x_proj: (5120,384) @ (44,384)^T -> dbl (5120,44) */
        gemm_kernel<<<dim3(1, 80), 256>>>(xc, DI, xproj_w + (size_t)l*44*DI,
                                          dbl, 44, NROWS, 44, DI, nullptr, 0);

        /* dt_proj + bias + softplus: (5120,12) @ (384,12)^T -> dt (5120,384) */
        gemm_kernel<<<dim3(6, 80), 256>>>(dbl, 44, dt_w + (size_t)l*DI*DR,
                                          dt, DI, NROWS, DI, DR, dt_b + l*DI, 1);

        scan1_kernel<<<dim3(NC, BB), DI>>>(dt, xc, dbl, A_log + (size_t)l*DI*DS,
                                           y, eend, S);
        carry_kernel<<<(BB*DI*DS + 255)/256, 256>>>(eend, S,
                                                    A_log + (size_t)l*DI*DS, cin);
        scan3_kernel<<<dim3(NC, BB), DI>>>(dt, dbl, A_log + (size_t)l*DI*DS,
                                           cin, xz, xc, D_skip + l*DI, y);

        /* out_proj: (5120,384) @ (192,384)^T -> hidden (5120,192) */
        gemm_kernel<<<dim3(3, 80), 256>>>(y, DI, out_w + (size_t)l*DM*DI,
                                          hidden, DM, NROWS, DM, DI, nullptr, 0);
    }

    addnorm_kernel<<<NROWS, 192>>>(hidden, res, fnorm_w, fnorm_b, out, 0);
}

// round 4
// speedup vs baseline: 1.4150x; 1.4150x over previous
#include <cuda_runtime.h>
#include <math.h>

#define BB 16
#define LL 320
#define DM 192
#define DI 384
#define DS 16
#define DR 12
#define DEPTH 24
#define NROWS (BB*LL)      /* 5120 */
#define NC 10
#define CL 32
#define LOG2E 1.4426950408889634f
#define EPSLN 1e-5f

typedef unsigned long long ull;

/* ---------------- scratch (static device globals; no allocation) -------- */
__device__ float g_hidden[NROWS*DM];
__device__ float g_res[NROWS*DM];
__device__ float g_hn[NROWS*DM];
__device__ float g_xz[NROWS*2*DI];
__device__ float g_xc[NROWS*DI];
__device__ float g_dbl[NROWS*44];
__device__ float g_dt[NROWS*DI];
__device__ float g_y[NROWS*DI];
__device__ float g_eend[BB*NC*DI*DS];
__device__ float g_S[BB*NC*DI];
__device__ float g_cin[BB*NC*DI*DS];

__device__ __forceinline__ void fma2(ull &d, ull a, ull b) {
    asm("fma.rn.f32x2 %0, %1, %2, %3;" : "=l"(d) : "l"(a), "l"(b), "l"(d));
}
__device__ __forceinline__ ull pack2(float v) {
    ull d;
    asm("mov.b64 %0, {%1, %1};" : "=l"(d) : "f"(v));
    return d;
}
__device__ __forceinline__ void unpack2(ull v, float &lo, float &hi) {
    asm("mov.b64 {%0, %1}, %2;" : "=f"(lo), "=f"(hi) : "l"(v));
}

/* ---------------- patch embed + pos, zero residual ---------------------- */
__global__ __launch_bounds__(192) void patch_kernel(
    const float* __restrict__ ximg, const float* __restrict__ zimg,
    const float* __restrict__ pw, const float* __restrict__ pb,
    const float* __restrict__ posx, const float* __restrict__ posz,
    float* __restrict__ hidden, float* __restrict__ res)
{
    __shared__ float sp[4][768];
    int tg = blockIdx.x, tid = threadIdx.x;
    for (int i = 0; i < 4; i++) {
        int r = tg*4 + i, b = r / LL, t = r % LL;
        for (int c = tid; c < 768; c += 192) {
            int ch = c >> 8, p = c & 255, py = p >> 4, px = p & 15;
            float v;
            if (t < 64) {
                int ph = (t >> 3)*16 + py, pwi = (t & 7)*16 + px;
                v = zimg[((b*3 + ch)*128 + ph)*128 + pwi];
            } else {
                int tx = t - 64;
                int ph = (tx >> 4)*16 + py, pwi = (tx & 15)*16 + px;
                v = ximg[((b*3 + ch)*256 + ph)*256 + pwi];
            }
            sp[i][c] = v;
        }
    }
    __syncthreads();
    int d = tid;
    float a0 = 0.f, a1 = 0.f, a2 = 0.f, a3 = 0.f;
    const float* wr = pw + d*768;
    for (int c = 0; c < 768; c++) {
        float w = wr[c];
        a0 = fmaf(w, sp[0][c], a0);
        a1 = fmaf(w, sp[1][c], a1);
        a2 = fmaf(w, sp[2][c], a2);
        a3 = fmaf(w, sp[3][c], a3);
    }
    float accs[4] = {a0, a1, a2, a3};
    for (int i = 0; i < 4; i++) {
        int r = tg*4 + i, t = r % LL;
        float pos = (t < 64) ? posz[t*DM + d] : posx[(t - 64)*DM + d];
        hidden[r*DM + d] = accs[i] + pb[d] + pos;
        res[r*DM + d] = 0.f;
    }
}

/* ---------------- fused add + layernorm --------------------------------- */
__global__ __launch_bounds__(192) void addnorm_kernel(
    const float* __restrict__ hid, float* __restrict__ res,
    const float* __restrict__ w, const float* __restrict__ b,
    float* __restrict__ o, int write_res)
{
    int row = blockIdx.x, d = threadIdx.x;
    float v = hid[row*DM + d] + res[row*DM + d];
    if (write_res) res[row*DM + d] = v;
    float s = v, sq = v*v;
    #pragma unroll
    for (int off = 16; off > 0; off >>= 1) {
        s  += __shfl_down_sync(0xffffffffu, s,  off);
        sq += __shfl_down_sync(0xffffffffu, sq, off);
    }
    __shared__ float sh1[6], sh2[6];
    int wid = d >> 5, lane = d & 31;
    if (lane == 0) { sh1[wid] = s; sh2[wid] = sq; }
    __syncthreads();
    float ts = 0.f, tq = 0.f;
    #pragma unroll
    for (int i = 0; i < 6; i++) { ts += sh1[i]; tq += sh2[i]; }
    float mean = ts * (1.f/DM);
    float var  = tq * (1.f/DM) - mean*mean;
    float rs = rsqrtf(var + EPSLN);
    o[row*DM + d] = (v - mean) * rs * w[d] + b[d];
}

/* ---------------- f32x2 packed GEMM: C[M,N] = A[M,K] @ W[N,K]^T ---------- */
/* compile-time shapes, double-buffered smem, FFMA2 inner loop.             */
/* EP: 0 = none, 1 = +bias then softplus. NG: guard N (loads + stores).     */
template<int BM, int BN, int BK, int TM, int TN, int KT, int EP, bool NG>
__global__ __launch_bounds__((BM/TM)*(BN/TN)) void gemm2_kernel(
    const float* __restrict__ A, int lda,
    const float* __restrict__ W,
    float* __restrict__ C, int ldc,
    int N, const float* __restrict__ bias)
{
    constexpr int NT  = (BM/TM)*(BN/TN);
    constexpr int BK4 = BK/4;
    constexpr int NA  = (BM*BK4 + NT - 1)/NT;
    constexpr int NW  = (BN*BK4 + NT - 1)/NT;
    constexpr int BMP = BM + 4, BNP = BN + 4;
    constexpr int T   = KT/BK;

    __shared__ __align__(16) float As[2][BK*BMP];
    __shared__ __align__(16) float Ws[2][BK*BNP];

    int tid = threadIdx.x;
    int bn = blockIdx.x * BN, bm = blockIdx.y * BM;
    int tx = tid % (BN/TN), ty = tid / (BN/TN);

    ull acc[TM][TN/2];
    #pragma unroll
    for (int i = 0; i < TM; i++)
        #pragma unroll
        for (int j = 0; j < TN/2; j++) acc[i][j] = 0ull;

    float4 ar[NA], wr[NW];

    /* load tile k0 into regs */
    #define LOAD_TILE(k0)                                                     \
        _Pragma("unroll")                                                     \
        for (int i = 0; i < NA; i++) {                                        \
            int e = tid + i*NT;                                               \
            if ((BM*BK4) % NT == 0 || e < BM*BK4) {                           \
                int m = e / BK4, kq = e % BK4;                                \
                ar[i] = *reinterpret_cast<const float4*>(                     \
                    &A[(size_t)(bm + m)*lda + (k0) + kq*4]);                  \
            }                                                                 \
        }                                                                     \
        _Pragma("unroll")                                                     \
        for (int i = 0; i < NW; i++) {                                        \
            int e = tid + i*NT;                                               \
            if ((BN*BK4) % NT == 0 || e < BN*BK4) {                           \
                int nn = e / BK4, kq = e % BK4;                               \
                if (NG && bn + nn >= N) wr[i] = make_float4(0.f,0.f,0.f,0.f); \
                else wr[i] = *reinterpret_cast<const float4*>(                \
                    &W[(size_t)(bn + nn)*KT + (k0) + kq*4]);                  \
            }                                                                 \
        }

    /* store regs into smem buffer bf (transposed) */
    #define STORE_TILE(bf)                                                    \
        _Pragma("unroll")                                                     \
        for (int i = 0; i < NA; i++) {                                        \
            int e = tid + i*NT;                                               \
            if ((BM*BK4) % NT == 0 || e < BM*BK4) {                           \
                int m = e / BK4, kq = e % BK4;                                \
                As[bf][(kq*4+0)*BMP + m] = ar[i].x;                           \
                As[bf][(kq*4+1)*BMP + m] = ar[i].y;                           \
                As[bf][(kq*4+2)*BMP + m] = ar[i].z;                           \
                As[bf][(kq*4+3)*BMP + m] = ar[i].w;                           \
            }                                                                 \
        }                                                                     \
        _Pragma("unroll")                                                     \
        for (int i = 0; i < NW; i++) {                                        \
            int e = tid + i*NT;                                               \
            if ((BN*BK4) % NT == 0 || e < BN*BK4) {                           \
                int nn = e / BK4, kq = e % BK4;                               \
                Ws[bf][(kq*4+0)*BNP + nn] = wr[i].x;                          \
                Ws[bf][(kq*4+1)*BNP + nn] = wr[i].y;                          \
                Ws[bf][(kq*4+2)*BNP + nn] = wr[i].z;                          \
                Ws[bf][(kq*4+3)*BNP + nn] = wr[i].w;                          \
            }                                                                 \
        }

    LOAD_TILE(0)
    STORE_TILE(0)
    __syncthreads();

    for (int t = 0; t < T; t++) {
        int buf = t & 1;
        if (t + 1 < T) { LOAD_TILE((t+1)*BK) }
        #pragma unroll
        for (int kk = 0; kk < BK; kk++) {
            float av[TM];
            #pragma unroll
            for (int i4 = 0; i4 < TM/4; i4++)
                *reinterpret_cast<float4*>(&av[i4*4]) =
                    *reinterpret_cast<const float4*>(&As[buf][kk*BMP + ty*TM + i4*4]);
            ull ad[TM];
            #pragma unroll
            for (int i = 0; i < TM; i++) ad[i] = pack2(av[i]);
            ull bv[TN/2];
            #pragma unroll
            for (int j = 0; j < TN/2; j++)
                bv[j] = *reinterpret_cast<const ull*>(&Ws[buf][kk*BNP + tx*TN + j*2]);
            #pragma unroll
            for (int i = 0; i < TM; i++)
                #pragma unroll
                for (int j = 0; j < TN/2; j++)
                    fma2(acc[i][j], ad[i], bv[j]);
        }
        if (t + 1 < T) { STORE_TILE(buf ^ 1) }
        __syncthreads();
    }

    #undef LOAD_TILE
    #undef STORE_TILE

    /* epilogue */
    #pragma unroll
    for (int i = 0; i < TM; i++) {
        int m = bm + ty*TM + i;
        float ov[TN];
        #pragma unroll
        for (int j = 0; j < TN/2; j++) unpack2(acc[i][j], ov[2*j], ov[2*j+1]);
        if (EP == 1) {
            #pragma unroll
            for (int jj = 0; jj < TN; jj++) {
                int n = bn + tx*TN + jj;
                float v = ov[jj] + bias[n];
                ov[jj] = (v > 20.f) ? v : log1pf(expf(v));
            }
        }
        if (NG) {
            #pragma unroll
            for (int jj = 0; jj < TN; jj++) {
                int n = bn + tx*TN + jj;
                if (n < N) C[(size_t)m*ldc + n] = ov[jj];
            }
        } else {
            #pragma unroll
            for (int j4 = 0; j4 < TN/4; j4++)
                *reinterpret_cast<float4*>(&C[(size_t)m*ldc + bn + tx*TN + j4*4]) =
                    *reinterpret_cast<const float4*>(&ov[j4*4]);
        }
    }
}

/* ---------------- causal depthwise conv + silu -------------------------- */
__global__ __launch_bounds__(256) void conv_silu_kernel(
    const float* __restrict__ xz, const float* __restrict__ cw,
    const float* __restrict__ cb, float* __restrict__ xc)
{
    int idx = blockIdx.x*blockDim.x + threadIdx.x;
    if (idx >= NROWS*DI) return;
    int d = idx % DI, r = idx / DI;
    int b = r / LL, l = r % LL;
    float acc = cb[d];
    #pragma unroll
    for (int j = 0; j < 4; j++) {
        int ls = l - 3 + j;
        if (ls >= 0)
            acc = fmaf(xz[(size_t)(b*LL + ls)*(2*DI) + d], cw[d*4 + j], acc);
    }
    float sig = 1.f / (1.f + expf(-acc));
    xc[idx] = acc * sig;
}

/* ---------------- scan pass 1: chunk-local scan ------------------------- */
__global__ __launch_bounds__(DI) void scan1_kernel(
    const float* __restrict__ dt, const float* __restrict__ xc,
    const float* __restrict__ dbl, const float* __restrict__ A_log,
    float* __restrict__ y, float* __restrict__ eend, float* __restrict__ S)
{
    int b = blockIdx.y, ck = blockIdx.x, d = threadIdx.x;
    __shared__ float sB[CL][DS], sC[CL][DS];
    for (int e = d; e < CL*DS; e += DI) {
        int l = e >> 4, n = e & 15;
        const float* row = dbl + (size_t)(b*LL + ck*CL + l)*44;
        sB[l][n] = row[12 + n];
        sC[l][n] = row[28 + n];
    }
    __syncthreads();
    float cn[DS], h[DS];
    const float* al = A_log + d*DS;
    #pragma unroll
    for (int n = 0; n < DS; n++) { cn[n] = -expf(al[n]) * LOG2E; h[n] = 0.f; }
    float Ss = 0.f;
    int base = (b*LL + ck*CL)*DI + d;
    for (int l = 0; l < CL; l++) {
        float dtv = dt[base + l*DI];
        float xcv = xc[base + l*DI];
        Ss += dtv;
        float u = dtv * xcv;
        float acc = 0.f;
        #pragma unroll
        for (int n = 0; n < DS; n++) {
            float e2 = exp2f(dtv * cn[n]);
            h[n] = fmaf(e2, h[n], u * sB[l][n]);
            acc = fmaf(h[n], sC[l][n], acc);
        }
        y[base + l*DI] = acc;
    }
    int si = (b*NC + ck)*DI + d;
    S[si] = Ss;
    #pragma unroll
    for (int n = 0; n < DS; n++) eend[(size_t)si*DS + n] = h[n];
}

/* ---------------- carry propagation across chunks ----------------------- */
__global__ __launch_bounds__(256) void carry_kernel(
    const float* __restrict__ eend, const float* __restrict__ S,
    const float* __restrict__ A_log, float* __restrict__ cin)
{
    int idx = blockIdx.x*blockDim.x + threadIdx.x;
    if (idx >= BB*DI*DS) return;
    int n = idx & 15, d = (idx >> 4) % DI, b = idx / (DI*DS);
    float cf = -expf(A_log[d*DS + n]) * LOG2E;
    float c = 0.f;
    for (int k = 0; k < NC; k++) {
        int si = (b*NC + k)*DI + d;
        cin[(size_t)si*DS + n] = c;
        c = fmaf(exp2f(S[si] * cf), c, eend[(size_t)si*DS + n]);
    }
}

/* ---------------- scan pass 3: carry correction + D skip + z gate ------- */
__global__ __launch_bounds__(DI) void scan3_kernel(
    const float* __restrict__ dt, const float* __restrict__ dbl,
    const float* __restrict__ A_log, const float* __restrict__ cin,
    const float* __restrict__ xz, const float* __restrict__ xc,
    const float* __restrict__ Dsk, float* __restrict__ y)
{
    int b = blockIdx.y, ck = blockIdx.x, d = threadIdx.x;
    __shared__ float sC[CL][DS];
    for (int e = d; e < CL*DS; e += DI) {
        int l = e >> 4, n = e & 15;
        sC[l][n] = dbl[(size_t)(b*LL + ck*CL + l)*44 + 28 + n];
    }
    __syncthreads();
    float cn[DS], ci[DS];
    if (ck > 0) {
        const float* al = A_log + d*DS;
        const float* cp = cin + (size_t)((b*NC + ck)*DI + d)*DS;
        #pragma unroll
        for (int n = 0; n < DS; n++) { cn[n] = -expf(al[n]) * LOG2E; ci[n] = cp[n]; }
    }
    float Dv = Dsk[d];
    int base = (b*LL + ck*CL)*DI + d;
    float tau = 0.f;
    for (int l = 0; l < CL; l++) {
        float dtv = dt[base + l*DI];
        tau += dtv;
        float yv = y[base + l*DI];
        if (ck > 0) {
            #pragma unroll
            for (int n = 0; n < DS; n++)
                yv = fmaf(exp2f(tau * cn[n]) * ci[n], sC[l][n], yv);
        }
        yv = fmaf(xc[base + l*DI], Dv, yv);
        int row = b*LL + ck*CL + l;
        float zv = xz[(size_t)row*(2*DI) + DI + d];
        yv *= zv / (1.f + expf(-zv));
        y[base + l*DI] = yv;
    }
}

/* ---------------- host driver ------------------------------------------- */
extern "C" void kernel_launch(void* const* d_in, const int* in_sizes, int n_in,
                              void* d_out, int out_size)
{
    const float* x_img   = (const float*)d_in[0];
    const float* z_img   = (const float*)d_in[1];
    const float* patch_w = (const float*)d_in[2];
    const float* patch_b = (const float*)d_in[3];
    const float* pos_x   = (const float*)d_in[4];
    const float* pos_z   = (const float*)d_in[5];
    const float* ln_w    = (const float*)d_in[6];
    const float* ln_b    = (const float*)d_in[7];
    const float* in_w    = (const float*)d_in[8];
    const float* conv_w  = (const float*)d_in[9];
    const float* conv_b  = (const float*)d_in[10];
    const float* xproj_w = (const float*)d_in[11];
    const float* dt_w    = (const float*)d_in[12];
    const float* dt_b    = (const float*)d_in[13];
    const float* A_log   = (const float*)d_in[14];
    const float* D_skip  = (const float*)d_in[15];
    const float* out_w   = (const float*)d_in[16];
    const float* fnorm_w = (const float*)d_in[17];
    const float* fnorm_b = (const float*)d_in[18];
    float* out = (float*)d_out;

    float *hidden, *res, *hn, *xz, *xc, *dbl, *dt, *y, *eend, *S, *cin;
    cudaGetSymbolAddress((void**)&hidden, g_hidden);
    cudaGetSymbolAddress((void**)&res,    g_res);
    cudaGetSymbolAddress((void**)&hn,     g_hn);
    cudaGetSymbolAddress((void**)&xz,     g_xz);
    cudaGetSymbolAddress((void**)&xc,     g_xc);
    cudaGetSymbolAddress((void**)&dbl,    g_dbl);
    cudaGetSymbolAddress((void**)&dt,     g_dt);
    cudaGetSymbolAddress((void**)&y,      g_y);
    cudaGetSymbolAddress((void**)&eend,   g_eend);
    cudaGetSymbolAddress((void**)&S,      g_S);
    cudaGetSymbolAddress((void**)&cin,    g_cin);

    patch_kernel<<<NROWS/4, 192>>>(x_img, z_img, patch_w, patch_b,
                                   pos_x, pos_z, hidden, res);

    for (int l = 0; l < DEPTH; l++) {
        addnorm_kernel<<<NROWS, 192>>>(hidden, res, ln_w + l*DM, ln_b + l*DM, hn, 1);

        /* in_proj: (5120,192) @ (768,192)^T -> xz (5120,768) */
        gemm2_kernel<64,128,16,8,8,192,0,false><<<dim3(6, 80), 128>>>(
            hn, DM, in_w + (size_t)l*2*DI*DM, xz, 2*DI, 2*DI, nullptr);

        conv_silu_kernel<<<(NROWS*DI + 255)/256, 256>>>(xz, conv_w + l*DI*4,
                                                        conv_b + l*DI, xc);

        /* x_proj: (5120,384) @ (44,384)^T -> dbl (5120,44) */
        gemm2_kernel<64,64,16,4,8,384,0,true><<<dim3(1, 80), 128>>>(
            xc, DI, xproj_w + (size_t)l*44*DI, dbl, 44, 44, nullptr);

        /* dt_proj + bias + softplus: (5120,12) @ (384,12)^T -> dt (5120,384) */
        gemm2_kernel<64,64,12,4,8,12,1,false><<<dim3(6, 80), 128>>>(
            dbl, 44, dt_w + (size_t)l*DI*DR, dt, DI, DI, dt_b + l*DI);

        scan1_kernel<<<dim3(NC, BB), DI>>>(dt, xc, dbl, A_log + (size_t)l*DI*DS,
                                           y, eend, S);
        carry_kernel<<<(BB*DI*DS + 255)/256, 256>>>(eend, S,
                                                    A_log + (size_t)l*DI*DS, cin);
        scan3_kernel<<<dim3(NC, BB), DI>>>(dt, dbl, A_log + (size_t)l*DI*DS,
                                           cin, xz, xc, D_skip + l*DI, y);

        /* out_proj: (5120,384) @ (192,384)^T -> hidden (5120,192) */
        gemm2_kernel<64,64,16,4,8,384,0,false><<<dim3(3, 80), 128>>>(
            y, DI, out_w + (size_t)l*DM*DI, hidden, DM, DM, nullptr);
    }

    addnorm_kernel<<<NROWS, 192>>>(hidden, res, fnorm_w, fnorm_b, out, 0);
}